// round 13
// baseline (speedup 1.0000x reference)
#include <cuda_runtime.h>

#define DD 128
#define HH 160
#define WW 160
#define W4 40                      // WW / 4
#define HWX (HH * WW)              // 25600
#define HW4 (HH * W4)              // 6400 float4 per slice
#define NV  (DD * HWX)             // 3276800
#define NV4 (DD * HW4)             // 819200 float4 per channel
#define NITER 10

// Gaussian weights: exp(-x^2/2), x in [-2,2], normalized
#define GW0 0.40261995f
#define GW1 0.24420134f
#define GW2 0.05448868f

// Scratch (device globals: allocation-free)
static __device__ float g_sum[NV];
static __device__ float g_vfA[3 * NV];
static __device__ float g_vfB[3 * NV];
static __device__ float g_vfC[3 * NV];

__device__ __forceinline__ float movAt(const float* __restrict__ m, int d, int h, int w) {
    if ((unsigned)d >= DD || (unsigned)h >= HH || (unsigned)w >= WW) return 0.0f;
    return __ldg(m + (d * HH + h) * WW + w);
}

__device__ __forceinline__ float trilerp(const float* __restrict__ mov,
                                         float cd, float ch, float cw) {
    int d0 = __float2int_rd(cd);
    int h0 = __float2int_rd(ch);
    int w0 = __float2int_rd(cw);
    float td = cd - (float)d0, th = ch - (float)h0, tw = cw - (float)w0;

    float m000, m001, m010, m011, m100, m101, m110, m111;
    if ((unsigned)d0 < DD - 1 && (unsigned)h0 < HH - 1 && (unsigned)w0 < WW - 1) {
        const float* p = mov + (d0 * HH + h0) * WW + w0;
        m000 = __ldg(p);             m001 = __ldg(p + 1);
        m010 = __ldg(p + WW);        m011 = __ldg(p + WW + 1);
        m100 = __ldg(p + HWX);       m101 = __ldg(p + HWX + 1);
        m110 = __ldg(p + HWX + WW);  m111 = __ldg(p + HWX + WW + 1);
    } else {
        m000 = movAt(mov, d0,   h0,   w0);   m001 = movAt(mov, d0,   h0,   w0+1);
        m010 = movAt(mov, d0,   h0+1, w0);   m011 = movAt(mov, d0,   h0+1, w0+1);
        m100 = movAt(mov, d0+1, h0,   w0);   m101 = movAt(mov, d0+1, h0,   w0+1);
        m110 = movAt(mov, d0+1, h0+1, w0);   m111 = movAt(mov, d0+1, h0+1, w0+1);
    }

    float c00 = m000 * (1.f-tw) + m001 * tw;
    float c01 = m010 * (1.f-tw) + m011 * tw;
    float c10 = m100 * (1.f-tw) + m101 * tw;
    float c11 = m110 * (1.f-tw) + m111 * tw;
    return (c00*(1.f-th) + c01*th) * (1.f-td) + (c10*(1.f-th) + c11*th) * td;
}

// ---------------------------------------------------------------------------
// FUSED smoothD + warp: each thread owns (h, w) and marches FDSEG d-values,
// holding the 5-tap D window for all 3 vfC channels in registers.
// Per d: vfA = D-smooth(vfC) (stored for force), then trilinear gather at
// grid+vfA, sum = warped + fix.  Lanes = consecutive w (unit-stride gather).
// ---------------------------------------------------------------------------
#define FDSEG 8
#define NFD (DD / FDSEG)    // 16

__global__ void __launch_bounds__(256) fusedDwarp_kernel(const float* __restrict__ mov,
                                                         const float* __restrict__ fix,
                                                         const float* __restrict__ vfc,
                                                         float* __restrict__ vfA,
                                                         float* __restrict__ sum) {
    int gwarp = (blockIdx.x * 256 + threadIdx.x) >> 5;   // < NFD * HH * 5
    int lane  = threadIdx.x & 31;
    int wseg = gwarp % 5;
    int h    = (gwarp / 5) % HH;
    int seg  = gwarp / (5 * HH);
    int w    = wseg * 32 + lane;
    int colbase = h * WW + w;
    int d0 = seg * FDSEG;

    const float* b0 = vfc + colbase;            // channel 0
    const float* b1 = vfc + NV + colbase;       // channel 1
    const float* b2 = vfc + 2 * NV + colbase;   // channel 2

    // 5-tap windows (d0-2 .. d0+2), zero-padded at D edges
    float w00, w01, w02, w03, w04;
    float w10, w11, w12, w13, w14;
    float w20, w21, w22, w23, w24;
    if (d0 >= 2) { w00 = __ldg(b0 + (d0-2)*HWX); w10 = __ldg(b1 + (d0-2)*HWX); w20 = __ldg(b2 + (d0-2)*HWX); }
    else         { w00 = 0.f; w10 = 0.f; w20 = 0.f; }
    if (d0 >= 1) { w01 = __ldg(b0 + (d0-1)*HWX); w11 = __ldg(b1 + (d0-1)*HWX); w21 = __ldg(b2 + (d0-1)*HWX); }
    else         { w01 = 0.f; w11 = 0.f; w21 = 0.f; }
    w02 = __ldg(b0 + d0*HWX);     w12 = __ldg(b1 + d0*HWX);     w22 = __ldg(b2 + d0*HWX);
    w03 = __ldg(b0 + (d0+1)*HWX); w13 = __ldg(b1 + (d0+1)*HWX); w23 = __ldg(b2 + (d0+1)*HWX);
    w04 = __ldg(b0 + (d0+2)*HWX); w14 = __ldg(b1 + (d0+2)*HWX); w24 = __ldg(b2 + (d0+2)*HWX);

    #pragma unroll
    for (int dd = 0; dd < FDSEG; ++dd) {
        int d = d0 + dd;
        int i = d * HWX + colbase;

        float v0 = GW2*(w00 + w04) + GW1*(w01 + w03) + GW0*w02;
        float v1 = GW2*(w10 + w14) + GW1*(w11 + w13) + GW0*w12;
        float v2 = GW2*(w20 + w24) + GW1*(w21 + w23) + GW0*w22;

        vfA[i]          = v0;
        vfA[NV + i]     = v1;
        vfA[2 * NV + i] = v2;

        float wv = trilerp(mov, (float)d + v0, (float)h + v1, (float)w + v2);
        sum[i] = wv + __ldg(fix + i);

        // slide windows
        w00 = w01; w01 = w02; w02 = w03; w03 = w04;
        w10 = w11; w11 = w12; w12 = w13; w13 = w14;
        w20 = w21; w21 = w22; w22 = w23; w23 = w24;
        if (d + 3 < DD) {
            w04 = __ldg(b0 + (d+3)*HWX);
            w14 = __ldg(b1 + (d+3)*HWX);
            w24 = __ldg(b2 + (d+3)*HWX);
        } else {
            w04 = 0.f; w14 = 0.f; w24 = 0.f;
        }
    }
}

// ---------------------------------------------------------------------------
// Shared demons math
// ---------------------------------------------------------------------------
__device__ __forceinline__ void demons_update(
    int w4, int h, int d,
    float4 sm, float4 sl, float4 sr, float4 su, float4 sd, float4 sf, float4 sb,
    float4 fx, float4 v0, float4 v1, float4 v2,
    float4& o0, float4& o1, float4& o2)
{
    #pragma unroll
    for (int j = 0; j < 4; ++j) {
        int w = w4 * 4 + j;
        float smj = ((const float*)&sm)[j];

        float left  = (j > 0) ? ((const float*)&sm)[j-1] : sl.w;
        float right = (j < 3) ? ((const float*)&sm)[j+1] : sr.x;
        float g2 = (w == 0) ? (right - smj) : (w == WW-1) ? (smj - left) : 0.5f * (right - left);

        float up = ((const float*)&su)[j], dn = ((const float*)&sd)[j];
        float g1 = (h == 0) ? (dn - smj) : (h == HH-1) ? (smj - up) : 0.5f * (dn - up);

        float fr = ((const float*)&sf)[j], bk = ((const float*)&sb)[j];
        float g0 = (d == 0) ? (bk - smj) : (d == DD-1) ? (smj - fr) : 0.5f * (bk - fr);

        float dv = smj - 2.0f * ((const float*)&fx)[j];   // warped - fix
        float denom = g0*g0 + g1*g1 + g2*g2 + dv*dv;
        float scale = (denom > 1e-6f) ? __fdividef(-dv, denom) : 0.0f;

        ((float*)&o0)[j] = ((const float*)&v0)[j] + scale * g0;
        ((float*)&o1)[j] = ((const float*)&v1)[j] + scale * g1;
        ((float*)&o2)[j] = ((const float*)&v2)[j] + scale * g2;
    }
}

// ---------------------------------------------------------------------------
// Force (iterations >= 1): i4-indexed flat kernel (measured best)
// ---------------------------------------------------------------------------
__global__ void __launch_bounds__(256) force_kernel4(const float4* __restrict__ s,
                                                     const float4* __restrict__ fix,
                                                     const float4* __restrict__ vf_in,
                                                     float4* __restrict__ vf_out) {
    int i4 = blockIdx.x * 256 + threadIdx.x;
    if (i4 >= NV4) return;
    int w4 = i4 % W4;
    int h  = (i4 / W4) % HH;
    int d  = i4 / HW4;

    const float4 z4 = make_float4(0.f, 0.f, 0.f, 0.f);
    float4 sm = s[i4];
    float4 sl = (w4 > 0)      ? s[i4 - 1]   : z4;
    float4 sr = (w4 < W4 - 1) ? s[i4 + 1]   : z4;
    float4 su = (h  > 0)      ? s[i4 - W4]  : z4;
    float4 sd = (h  < HH - 1) ? s[i4 + W4]  : z4;
    float4 sf = (d  > 0)      ? s[i4 - HW4] : z4;
    float4 sb = (d  < DD - 1) ? s[i4 + HW4] : z4;
    float4 fx = fix[i4];

    float4 v0 = vf_in[i4], v1 = vf_in[NV4 + i4], v2 = vf_in[2 * NV4 + i4];
    float4 o0, o1, o2;
    demons_update(w4, h, d, sm, sl, sr, su, sd, sf, sb, fx, v0, v1, v2, o0, o1, o2);

    vf_out[i4]           = o0;
    vf_out[NV4 + i4]     = o1;
    vf_out[2 * NV4 + i4] = o2;
}

// ---------------------------------------------------------------------------
// Force iteration 0: vf == 0, warped == mov; sum computed inline.
// ---------------------------------------------------------------------------
__global__ void __launch_bounds__(256) force0_kernel4(const float4* __restrict__ mov,
                                                      const float4* __restrict__ fix,
                                                      float4* __restrict__ vf_out) {
    int i4 = blockIdx.x * 256 + threadIdx.x;
    if (i4 >= NV4) return;
    int w4 = i4 % W4;
    int h  = (i4 / W4) % HH;
    int d  = i4 / HW4;

    const float4 z4 = make_float4(0.f, 0.f, 0.f, 0.f);
    #define SUMLD(off) make_float4(mov[off].x + fix[off].x, mov[off].y + fix[off].y, \
                                   mov[off].z + fix[off].z, mov[off].w + fix[off].w)
    float4 sm = SUMLD(i4);
    float4 sl = (w4 > 0)      ? SUMLD(i4 - 1)   : z4;
    float4 sr = (w4 < W4 - 1) ? SUMLD(i4 + 1)   : z4;
    float4 su = (h  > 0)      ? SUMLD(i4 - W4)  : z4;
    float4 sd = (h  < HH - 1) ? SUMLD(i4 + W4)  : z4;
    float4 sf = (d  > 0)      ? SUMLD(i4 - HW4) : z4;
    float4 sb = (d  < DD - 1) ? SUMLD(i4 + HW4) : z4;
    #undef SUMLD
    float4 fx = fix[i4];

    float4 o0, o1, o2;
    demons_update(w4, h, d, sm, sl, sr, su, sd, sf, sb, fx, z4, z4, z4, o0, o1, o2);

    vf_out[i4]           = o0;
    vf_out[NV4 + i4]     = o1;
    vf_out[2 * NV4 + i4] = o2;
}

// ---------------------------------------------------------------------------
// Fused W+H Gaussian smoothing, single smem buffer.
// ---------------------------------------------------------------------------
#define TROWS 36
#define IROWS 32
#define NT_HW 5   // 160 / 32

__global__ void __launch_bounds__(256) smoothHW_kernel(const float4* __restrict__ in,
                                                       float4* __restrict__ out) {
    __shared__ float4 s1[TROWS * W4];

    int b  = blockIdx.x;
    int ht = b % NT_HW;
    int d  = (b / NT_HW) % DD;
    int c  = b / (NT_HW * DD);
    int h0 = ht * IROWS;

    const float4* src = in  + (size_t)c * NV4 + (size_t)d * HW4;
    float4*       dst = out + (size_t)c * NV4 + (size_t)d * HW4;
    const float4 z4 = make_float4(0.f, 0.f, 0.f, 0.f);

    for (int t = threadIdx.x; t < TROWS * W4; t += 256) {
        int r  = t / W4;
        int cc = t % W4;
        int hg = h0 - 2 + r;
        float4 o;
        if ((unsigned)hg < HH) {
            const float4* row = src + hg * W4;
            float4 m = __ldg(row + cc);
            float4 l = (cc > 0)      ? __ldg(row + cc - 1) : z4;
            float4 r2 = (cc < W4 - 1) ? __ldg(row + cc + 1) : z4;
            o.x = GW2*l.z + GW1*l.w + GW0*m.x + GW1*m.y + GW2*m.z;
            o.y = GW2*l.w + GW1*m.x + GW0*m.y + GW1*m.z + GW2*m.w;
            o.z = GW2*m.x + GW1*m.y + GW0*m.z + GW1*m.w + GW2*r2.x;
            o.w = GW2*m.y + GW1*m.z + GW0*m.w + GW1*r2.x + GW2*r2.y;
        } else {
            o = z4;
        }
        s1[t] = o;
    }
    __syncthreads();

    for (int t = threadIdx.x; t < IROWS * W4; t += 256) {
        int r  = t / W4 + 2;
        int cc = t % W4;
        float4 a = s1[(r - 2) * W4 + cc];
        float4 b2 = s1[(r - 1) * W4 + cc];
        float4 m = s1[r * W4 + cc];
        float4 e = s1[(r + 1) * W4 + cc];
        float4 f = s1[(r + 2) * W4 + cc];
        float4 o;
        o.x = GW2*(a.x + f.x) + GW1*(b2.x + e.x) + GW0*m.x;
        o.y = GW2*(a.y + f.y) + GW1*(b2.y + e.y) + GW0*m.y;
        o.z = GW2*(a.z + f.z) + GW1*(b2.z + e.z) + GW0*m.z;
        o.w = GW2*(a.w + f.w) + GW1*(b2.w + e.w) + GW0*m.w;
        dst[(h0 + r - 2) * W4 + cc] = o;
    }
}

// ---------------------------------------------------------------------------
// Final D-axis smoothing (once): 2 column streams per thread, 16 outputs each.
// ---------------------------------------------------------------------------
#define DSEG 16
#define NDSEG (DD / DSEG)   // 8
#define HALFC (HW4 / 2)     // 3200

__global__ void __launch_bounds__(256) smoothD_slide2(const float4* __restrict__ in,
                                                      float4* __restrict__ out) {
    int gid = blockIdx.x * 256 + threadIdx.x;
    int col = gid % HALFC;
    int seg = (gid / HALFC) % NDSEG;
    int c   = gid / (HALFC * NDSEG);
    const float4 z4 = make_float4(0.f, 0.f, 0.f, 0.f);

    const float4* pa = in  + (size_t)c * NV4 + col;
    const float4* pb = pa + HALFC;
    float4*       qa = out + (size_t)c * NV4 + col;
    float4*       qb = qa + HALFC;
    int d0 = seg * DSEG;

    float4 a0, a1, a2, a3, a4, b0, b1, b2, b3, b4;
    if (d0 >= 2) { a0 = pa[(size_t)(d0-2)*HW4]; b0 = pb[(size_t)(d0-2)*HW4]; }
    else         { a0 = z4; b0 = z4; }
    if (d0 >= 1) { a1 = pa[(size_t)(d0-1)*HW4]; b1 = pb[(size_t)(d0-1)*HW4]; }
    else         { a1 = z4; b1 = z4; }
    a2 = pa[(size_t)d0*HW4];     b2 = pb[(size_t)d0*HW4];
    a3 = pa[(size_t)(d0+1)*HW4]; b3 = pb[(size_t)(d0+1)*HW4];
    a4 = pa[(size_t)(d0+2)*HW4]; b4 = pb[(size_t)(d0+2)*HW4];

    #pragma unroll
    for (int dd = 0; dd < DSEG; ++dd) {
        int d = d0 + dd;
        float4 oa, ob;
        oa.x = GW2*(a0.x + a4.x) + GW1*(a1.x + a3.x) + GW0*a2.x;
        oa.y = GW2*(a0.y + a4.y) + GW1*(a1.y + a3.y) + GW0*a2.y;
        oa.z = GW2*(a0.z + a4.z) + GW1*(a1.z + a3.z) + GW0*a2.z;
        oa.w = GW2*(a0.w + a4.w) + GW1*(a1.w + a3.w) + GW0*a2.w;
        ob.x = GW2*(b0.x + b4.x) + GW1*(b1.x + b3.x) + GW0*b2.x;
        ob.y = GW2*(b0.y + b4.y) + GW1*(b1.y + b3.y) + GW0*b2.y;
        ob.z = GW2*(b0.z + b4.z) + GW1*(b1.z + b3.z) + GW0*b2.z;
        ob.w = GW2*(b0.w + b4.w) + GW1*(b1.w + b3.w) + GW0*b2.w;
        qa[(size_t)d * HW4] = oa;
        qb[(size_t)d * HW4] = ob;
        a0 = a1; a1 = a2; a2 = a3; a3 = a4;
        b0 = b1; b1 = b2; b2 = b3; b3 = b4;
        if (d + 3 < DD) {
            a4 = pa[(size_t)(d + 3) * HW4];
            b4 = pb[(size_t)(d + 3) * HW4];
        } else {
            a4 = z4; b4 = z4;
        }
    }
}

extern "C" void kernel_launch(void* const* d_in, const int* in_sizes, int n_in,
                              void* d_out, int out_size) {
    const float* mov = (const float*)d_in[0];
    const float* fixf = (const float*)d_in[1];
    const float4* fix = (const float4*)d_in[1];
    float4* out4 = (float4*)d_out;

    float *vfA, *vfB, *vfC, *sum;
    cudaGetSymbolAddress((void**)&vfA, g_vfA);
    cudaGetSymbolAddress((void**)&vfB, g_vfB);
    cudaGetSymbolAddress((void**)&vfC, g_vfC);
    cudaGetSymbolAddress((void**)&sum, g_sum);

    const int blocksN4  = NV4 / 256;                   // 3200
    const int blocksHW  = 3 * DD * NT_HW;              // 1920
    const int blocksD   = (3 * NDSEG * HALFC) / 256;   // 300
    const int blocksFD  = (NFD * HH * 5 * 32) / 256;   // 1600

    for (int it = 0; it < NITER; ++it) {
        if (it == 0) {
            force0_kernel4<<<blocksN4, 256>>>((const float4*)mov, fix, (float4*)vfB);
        } else {
            // fused: vfA = D-smooth(vfC);  sum = warp(mov, grid+vfA) + fix
            fusedDwarp_kernel<<<blocksFD, 256>>>(mov, fixf, vfC, vfA, sum);
            force_kernel4<<<blocksN4, 256>>>((const float4*)sum, fix,
                                             (const float4*)vfA, (float4*)vfB);
        }
        smoothHW_kernel<<<blocksHW, 256>>>((const float4*)vfB, (float4*)vfC);
    }
    // Final D-pass: out = D-smooth(vfC)
    smoothD_slide2<<<blocksD, 256>>>((const float4*)vfC, out4);
}

// round 14
// speedup vs baseline: 1.1183x; 1.1183x over previous
#include <cuda_runtime.h>

#define DD 128
#define HH 160
#define WW 160
#define W4 40                      // WW / 4
#define HWX (HH * WW)              // 25600
#define HW4 (HH * W4)              // 6400 float4 per slice
#define NV  (DD * HWX)             // 3276800
#define NV4 (DD * HW4)             // 819200 float4 per channel
#define NITER 10

// Gaussian weights: exp(-x^2/2), x in [-2,2], normalized
#define GW0 0.40261995f
#define GW1 0.24420134f
#define GW2 0.05448868f

// Scratch (device globals: allocation-free)
static __device__ float g_sum[NV];
static __device__ float g_vfA[3 * NV];
static __device__ float g_vfB[3 * NV];
static __device__ float g_vfC[3 * NV];

__device__ __forceinline__ float movAt(const float* __restrict__ m, int d, int h, int w) {
    if ((unsigned)d >= DD || (unsigned)h >= HH || (unsigned)w >= WW) return 0.0f;
    return __ldg(m + (d * HH + h) * WW + w);
}

// ---------------------------------------------------------------------------
// Warp pass, row-per-warp layout, 3-phase: batched coalesced loads ->
// coordinate math -> 5 independent gather blocks -> stores.
// ---------------------------------------------------------------------------
__global__ void __launch_bounds__(256) warp_kernel_row(const float* __restrict__ mov,
                                                       const float* __restrict__ fix,
                                                       const float* __restrict__ vf,
                                                       float* __restrict__ sum) {
    int gwarp = (blockIdx.x * 256 + threadIdx.x) >> 5;   // row id (uniform per warp)
    int lane  = threadIdx.x & 31;
    if (gwarp >= DD * HH) return;
    int d = gwarp / HH;          // warp-uniform
    int h = gwarp - d * HH;
    int rowbase = gwarp * WW;

    // Phase 1: batched coalesced loads (20 outstanding)
    float vd[5], vh[5], vw[5], fxv[5];
    #pragma unroll
    for (int j = 0; j < 5; ++j) {
        int i = rowbase + lane + j * 32;
        vd[j]  = __ldg(vf + i);
        vh[j]  = __ldg(vf + NV + i);
        vw[j]  = __ldg(vf + 2 * NV + i);
        fxv[j] = __ldg(fix + i);
    }

    // Phase 2: coordinate math for all 5 samples
    float td[5], th[5], tw[5];
    int   d0[5], h0[5], w0[5];
    #pragma unroll
    for (int j = 0; j < 5; ++j) {
        float cd = (float)d + vd[j];
        float ch = (float)h + vh[j];
        float cw = (float)(lane + j * 32) + vw[j];
        d0[j] = __float2int_rd(cd);
        h0[j] = __float2int_rd(ch);
        w0[j] = __float2int_rd(cw);
        td[j] = cd - (float)d0[j];
        th[j] = ch - (float)h0[j];
        tw[j] = cw - (float)w0[j];
    }

    // Phase 3: 5 independent gather + lerp blocks
    float res[5];
    #pragma unroll
    for (int j = 0; j < 5; ++j) {
        float m000, m001, m010, m011, m100, m101, m110, m111;
        if ((unsigned)d0[j] < DD - 1 && (unsigned)h0[j] < HH - 1 && (unsigned)w0[j] < WW - 1) {
            const float* p = mov + (d0[j] * HH + h0[j]) * WW + w0[j];
            m000 = __ldg(p);             m001 = __ldg(p + 1);
            m010 = __ldg(p + WW);        m011 = __ldg(p + WW + 1);
            m100 = __ldg(p + HWX);       m101 = __ldg(p + HWX + 1);
            m110 = __ldg(p + HWX + WW);  m111 = __ldg(p + HWX + WW + 1);
        } else {
            m000 = movAt(mov, d0[j],   h0[j],   w0[j]);   m001 = movAt(mov, d0[j],   h0[j],   w0[j]+1);
            m010 = movAt(mov, d0[j],   h0[j]+1, w0[j]);   m011 = movAt(mov, d0[j],   h0[j]+1, w0[j]+1);
            m100 = movAt(mov, d0[j]+1, h0[j],   w0[j]);   m101 = movAt(mov, d0[j]+1, h0[j],   w0[j]+1);
            m110 = movAt(mov, d0[j]+1, h0[j]+1, w0[j]);   m111 = movAt(mov, d0[j]+1, h0[j]+1, w0[j]+1);
        }
        float c00 = m000 * (1.f-tw[j]) + m001 * tw[j];
        float c01 = m010 * (1.f-tw[j]) + m011 * tw[j];
        float c10 = m100 * (1.f-tw[j]) + m101 * tw[j];
        float c11 = m110 * (1.f-tw[j]) + m111 * tw[j];
        res[j] = (c00*(1.f-th[j]) + c01*th[j]) * (1.f-td[j])
               + (c10*(1.f-th[j]) + c11*th[j]) * td[j];
    }

    #pragma unroll
    for (int j = 0; j < 5; ++j)
        sum[rowbase + lane + j * 32] = res[j] + fxv[j];
}

// ---------------------------------------------------------------------------
// Shared demons math
// ---------------------------------------------------------------------------
__device__ __forceinline__ void demons_update(
    int w4, int h, int d,
    float4 sm, float4 sl, float4 sr, float4 su, float4 sd, float4 sf, float4 sb,
    float4 fx, float4 v0, float4 v1, float4 v2,
    float4& o0, float4& o1, float4& o2)
{
    #pragma unroll
    for (int j = 0; j < 4; ++j) {
        int w = w4 * 4 + j;
        float smj = ((const float*)&sm)[j];

        float left  = (j > 0) ? ((const float*)&sm)[j-1] : sl.w;
        float right = (j < 3) ? ((const float*)&sm)[j+1] : sr.x;
        float g2 = (w == 0) ? (right - smj) : (w == WW-1) ? (smj - left) : 0.5f * (right - left);

        float up = ((const float*)&su)[j], dn = ((const float*)&sd)[j];
        float g1 = (h == 0) ? (dn - smj) : (h == HH-1) ? (smj - up) : 0.5f * (dn - up);

        float fr = ((const float*)&sf)[j], bk = ((const float*)&sb)[j];
        float g0 = (d == 0) ? (bk - smj) : (d == DD-1) ? (smj - fr) : 0.5f * (bk - fr);

        float dv = smj - 2.0f * ((const float*)&fx)[j];   // warped - fix
        float denom = g0*g0 + g1*g1 + g2*g2 + dv*dv;
        float scale = (denom > 1e-6f) ? __fdividef(-dv, denom) : 0.0f;

        ((float*)&o0)[j] = ((const float*)&v0)[j] + scale * g0;
        ((float*)&o1)[j] = ((const float*)&v1)[j] + scale * g1;
        ((float*)&o2)[j] = ((const float*)&v2)[j] + scale * g2;
    }
}

// ---------------------------------------------------------------------------
// Force (iterations >= 1): i4-indexed flat kernel, front-loaded
// ---------------------------------------------------------------------------
__global__ void __launch_bounds__(256) force_kernel4(const float4* __restrict__ s,
                                                     const float4* __restrict__ fix,
                                                     const float4* __restrict__ vf_in,
                                                     float4* __restrict__ vf_out) {
    int i4 = blockIdx.x * 256 + threadIdx.x;
    if (i4 >= NV4) return;
    int w4 = i4 % W4;
    int h  = (i4 / W4) % HH;
    int d  = i4 / HW4;

    const float4 z4 = make_float4(0.f, 0.f, 0.f, 0.f);
    // Front-load center streams first
    float4 fx = fix[i4];
    float4 v0 = vf_in[i4], v1 = vf_in[NV4 + i4], v2 = vf_in[2 * NV4 + i4];
    float4 sm = s[i4];
    float4 sl = (w4 > 0)      ? s[i4 - 1]   : z4;
    float4 sr = (w4 < W4 - 1) ? s[i4 + 1]   : z4;
    float4 su = (h  > 0)      ? s[i4 - W4]  : z4;
    float4 sd = (h  < HH - 1) ? s[i4 + W4]  : z4;
    float4 sf = (d  > 0)      ? s[i4 - HW4] : z4;
    float4 sb = (d  < DD - 1) ? s[i4 + HW4] : z4;

    float4 o0, o1, o2;
    demons_update(w4, h, d, sm, sl, sr, su, sd, sf, sb, fx, v0, v1, v2, o0, o1, o2);

    vf_out[i4]           = o0;
    vf_out[NV4 + i4]     = o1;
    vf_out[2 * NV4 + i4] = o2;
}

// ---------------------------------------------------------------------------
// Force iteration 0: vf == 0, warped == mov; sum computed inline.
// ---------------------------------------------------------------------------
__global__ void __launch_bounds__(256) force0_kernel4(const float4* __restrict__ mov,
                                                      const float4* __restrict__ fix,
                                                      float4* __restrict__ vf_out) {
    int i4 = blockIdx.x * 256 + threadIdx.x;
    if (i4 >= NV4) return;
    int w4 = i4 % W4;
    int h  = (i4 / W4) % HH;
    int d  = i4 / HW4;

    const float4 z4 = make_float4(0.f, 0.f, 0.f, 0.f);
    #define SUMLD(off) make_float4(mov[off].x + fix[off].x, mov[off].y + fix[off].y, \
                                   mov[off].z + fix[off].z, mov[off].w + fix[off].w)
    float4 sm = SUMLD(i4);
    float4 sl = (w4 > 0)      ? SUMLD(i4 - 1)   : z4;
    float4 sr = (w4 < W4 - 1) ? SUMLD(i4 + 1)   : z4;
    float4 su = (h  > 0)      ? SUMLD(i4 - W4)  : z4;
    float4 sd = (h  < HH - 1) ? SUMLD(i4 + W4)  : z4;
    float4 sf = (d  > 0)      ? SUMLD(i4 - HW4) : z4;
    float4 sb = (d  < DD - 1) ? SUMLD(i4 + HW4) : z4;
    #undef SUMLD
    float4 fx = fix[i4];

    float4 o0, o1, o2;
    demons_update(w4, h, d, sm, sl, sr, su, sd, sf, sb, fx, z4, z4, z4, o0, o1, o2);

    vf_out[i4]           = o0;
    vf_out[NV4 + i4]     = o1;
    vf_out[2 * NV4 + i4] = o2;
}

// ---------------------------------------------------------------------------
// Fused W+H Gaussian smoothing, single smem buffer.
// ---------------------------------------------------------------------------
#define TROWS 36
#define IROWS 32
#define NT_HW 5   // 160 / 32

__global__ void __launch_bounds__(256) smoothHW_kernel(const float4* __restrict__ in,
                                                       float4* __restrict__ out) {
    __shared__ float4 s1[TROWS * W4];

    int b  = blockIdx.x;
    int ht = b % NT_HW;
    int d  = (b / NT_HW) % DD;
    int c  = b / (NT_HW * DD);
    int h0 = ht * IROWS;

    const float4* src = in  + (size_t)c * NV4 + (size_t)d * HW4;
    float4*       dst = out + (size_t)c * NV4 + (size_t)d * HW4;
    const float4 z4 = make_float4(0.f, 0.f, 0.f, 0.f);

    for (int t = threadIdx.x; t < TROWS * W4; t += 256) {
        int r  = t / W4;
        int cc = t % W4;
        int hg = h0 - 2 + r;
        float4 o;
        if ((unsigned)hg < HH) {
            const float4* row = src + hg * W4;
            float4 m = __ldg(row + cc);
            float4 l = (cc > 0)      ? __ldg(row + cc - 1) : z4;
            float4 r2 = (cc < W4 - 1) ? __ldg(row + cc + 1) : z4;
            o.x = GW2*l.z + GW1*l.w + GW0*m.x + GW1*m.y + GW2*m.z;
            o.y = GW2*l.w + GW1*m.x + GW0*m.y + GW1*m.z + GW2*m.w;
            o.z = GW2*m.x + GW1*m.y + GW0*m.z + GW1*m.w + GW2*r2.x;
            o.w = GW2*m.y + GW1*m.z + GW0*m.w + GW1*r2.x + GW2*r2.y;
        } else {
            o = z4;
        }
        s1[t] = o;
    }
    __syncthreads();

    for (int t = threadIdx.x; t < IROWS * W4; t += 256) {
        int r  = t / W4 + 2;
        int cc = t % W4;
        float4 a = s1[(r - 2) * W4 + cc];
        float4 b2 = s1[(r - 1) * W4 + cc];
        float4 m = s1[r * W4 + cc];
        float4 e = s1[(r + 1) * W4 + cc];
        float4 f = s1[(r + 2) * W4 + cc];
        float4 o;
        o.x = GW2*(a.x + f.x) + GW1*(b2.x + e.x) + GW0*m.x;
        o.y = GW2*(a.y + f.y) + GW1*(b2.y + e.y) + GW0*m.y;
        o.z = GW2*(a.z + f.z) + GW1*(b2.z + e.z) + GW0*m.z;
        o.w = GW2*(a.w + f.w) + GW1*(b2.w + e.w) + GW0*m.w;
        dst[(h0 + r - 2) * W4 + cc] = o;
    }
}

// ---------------------------------------------------------------------------
// D-axis smoothing: 2 column streams per thread (2x MLP), 16 outputs each.
// ---------------------------------------------------------------------------
#define DSEG 16
#define NDSEG (DD / DSEG)   // 8
#define HALFC (HW4 / 2)     // 3200

__global__ void __launch_bounds__(256) smoothD_slide2(const float4* __restrict__ in,
                                                      float4* __restrict__ out) {
    int gid = blockIdx.x * 256 + threadIdx.x;
    int col = gid % HALFC;
    int seg = (gid / HALFC) % NDSEG;
    int c   = gid / (HALFC * NDSEG);
    const float4 z4 = make_float4(0.f, 0.f, 0.f, 0.f);

    const float4* pa = in  + (size_t)c * NV4 + col;
    const float4* pb = pa + HALFC;
    float4*       qa = out + (size_t)c * NV4 + col;
    float4*       qb = qa + HALFC;
    int d0 = seg * DSEG;

    float4 a0, a1, a2, a3, a4, b0, b1, b2, b3, b4;
    if (d0 >= 2) { a0 = pa[(size_t)(d0-2)*HW4]; b0 = pb[(size_t)(d0-2)*HW4]; }
    else         { a0 = z4; b0 = z4; }
    if (d0 >= 1) { a1 = pa[(size_t)(d0-1)*HW4]; b1 = pb[(size_t)(d0-1)*HW4]; }
    else         { a1 = z4; b1 = z4; }
    a2 = pa[(size_t)d0*HW4];     b2 = pb[(size_t)d0*HW4];
    a3 = pa[(size_t)(d0+1)*HW4]; b3 = pb[(size_t)(d0+1)*HW4];
    a4 = pa[(size_t)(d0+2)*HW4]; b4 = pb[(size_t)(d0+2)*HW4];

    #pragma unroll
    for (int dd = 0; dd < DSEG; ++dd) {
        int d = d0 + dd;
        float4 oa, ob;
        oa.x = GW2*(a0.x + a4.x) + GW1*(a1.x + a3.x) + GW0*a2.x;
        oa.y = GW2*(a0.y + a4.y) + GW1*(a1.y + a3.y) + GW0*a2.y;
        oa.z = GW2*(a0.z + a4.z) + GW1*(a1.z + a3.z) + GW0*a2.z;
        oa.w = GW2*(a0.w + a4.w) + GW1*(a1.w + a3.w) + GW0*a2.w;
        ob.x = GW2*(b0.x + b4.x) + GW1*(b1.x + b3.x) + GW0*b2.x;
        ob.y = GW2*(b0.y + b4.y) + GW1*(b1.y + b3.y) + GW0*b2.y;
        ob.z = GW2*(b0.z + b4.z) + GW1*(b1.z + b3.z) + GW0*b2.z;
        ob.w = GW2*(b0.w + b4.w) + GW1*(b1.w + b3.w) + GW0*b2.w;
        qa[(size_t)d * HW4] = oa;
        qb[(size_t)d * HW4] = ob;
        a0 = a1; a1 = a2; a2 = a3; a3 = a4;
        b0 = b1; b1 = b2; b2 = b3; b3 = b4;
        if (d + 3 < DD) {
            a4 = pa[(size_t)(d + 3) * HW4];
            b4 = pb[(size_t)(d + 3) * HW4];
        } else {
            a4 = z4; b4 = z4;
        }
    }
}

extern "C" void kernel_launch(void* const* d_in, const int* in_sizes, int n_in,
                              void* d_out, int out_size) {
    const float* mov = (const float*)d_in[0];
    const float* fixf = (const float*)d_in[1];
    const float4* fix = (const float4*)d_in[1];
    float4* out4 = (float4*)d_out;

    float *vfA, *vfB, *vfC, *sum;
    cudaGetSymbolAddress((void**)&vfA, g_vfA);
    cudaGetSymbolAddress((void**)&vfB, g_vfB);
    cudaGetSymbolAddress((void**)&vfC, g_vfC);
    cudaGetSymbolAddress((void**)&sum, g_sum);

    const int blocksN4  = NV4 / 256;                   // 3200
    const int blocksHW  = 3 * DD * NT_HW;              // 1920
    const int blocksD   = (3 * NDSEG * HALFC) / 256;   // 300
    const int blocksRow = (DD * HH) / 8;               // 2560 (8 warps/block)

    for (int it = 0; it < NITER; ++it) {
        if (it == 0) {
            force0_kernel4<<<blocksN4, 256>>>((const float4*)mov, fix, (float4*)vfB);
        } else {
            warp_kernel_row<<<blocksRow, 256>>>(mov, fixf, vfA, sum);
            force_kernel4<<<blocksN4, 256>>>((const float4*)sum, fix,
                                             (const float4*)vfA, (float4*)vfB);
        }
        smoothHW_kernel<<<blocksHW, 256>>>((const float4*)vfB, (float4*)vfC);
        float4* dst = (it == NITER - 1) ? out4 : (float4*)vfA;
        smoothD_slide2<<<blocksD, 256>>>((const float4*)vfC, dst);
    }
}

// round 15
// speedup vs baseline: 1.1549x; 1.0328x over previous
#include <cuda_runtime.h>

#define DD 128
#define HH 160
#define WW 160
#define W4 40                      // WW / 4
#define HWX (HH * WW)              // 25600
#define HW4 (HH * W4)              // 6400 float4 per slice
#define NV  (DD * HWX)             // 3276800
#define NV4 (DD * HW4)             // 819200 float4 per channel
#define NITER 10

// Gaussian weights: exp(-x^2/2), x in [-2,2], normalized
#define GW0 0.40261995f
#define GW1 0.24420134f
#define GW2 0.05448868f

// Scratch (device globals: allocation-free).
// NOTE: no vfB — force updates vfA in place (center-only vf access),
// keeping the per-iteration L2 working set under the 126MB L2 capacity.
static __device__ float g_sum[NV];
static __device__ float g_vfA[3 * NV];
static __device__ float g_vfC[3 * NV];

__device__ __forceinline__ float movAt(const float* __restrict__ m, int d, int h, int w) {
    if ((unsigned)d >= DD || (unsigned)h >= HH || (unsigned)w >= WW) return 0.0f;
    return __ldg(m + (d * HH + h) * WW + w);
}

// ---------------------------------------------------------------------------
// Warp pass, row-per-warp layout, 3-phase: batched coalesced loads ->
// coordinate math -> 5 independent gather blocks -> stores.
// ---------------------------------------------------------------------------
__global__ void __launch_bounds__(256) warp_kernel_row(const float* __restrict__ mov,
                                                       const float* __restrict__ fix,
                                                       const float* __restrict__ vf,
                                                       float* __restrict__ sum) {
    int gwarp = (blockIdx.x * 256 + threadIdx.x) >> 5;   // row id (uniform per warp)
    int lane  = threadIdx.x & 31;
    if (gwarp >= DD * HH) return;
    int d = gwarp / HH;          // warp-uniform
    int h = gwarp - d * HH;
    int rowbase = gwarp * WW;

    // Phase 1: batched coalesced loads (20 outstanding)
    float vd[5], vh[5], vw[5], fxv[5];
    #pragma unroll
    for (int j = 0; j < 5; ++j) {
        int i = rowbase + lane + j * 32;
        vd[j]  = __ldg(vf + i);
        vh[j]  = __ldg(vf + NV + i);
        vw[j]  = __ldg(vf + 2 * NV + i);
        fxv[j] = __ldg(fix + i);
    }

    // Phase 2: coordinate math for all 5 samples
    float td[5], th[5], tw[5];
    int   d0[5], h0[5], w0[5];
    #pragma unroll
    for (int j = 0; j < 5; ++j) {
        float cd = (float)d + vd[j];
        float ch = (float)h + vh[j];
        float cw = (float)(lane + j * 32) + vw[j];
        d0[j] = __float2int_rd(cd);
        h0[j] = __float2int_rd(ch);
        w0[j] = __float2int_rd(cw);
        td[j] = cd - (float)d0[j];
        th[j] = ch - (float)h0[j];
        tw[j] = cw - (float)w0[j];
    }

    // Phase 3: 5 independent gather + lerp blocks
    float res[5];
    #pragma unroll
    for (int j = 0; j < 5; ++j) {
        float m000, m001, m010, m011, m100, m101, m110, m111;
        if ((unsigned)d0[j] < DD - 1 && (unsigned)h0[j] < HH - 1 && (unsigned)w0[j] < WW - 1) {
            const float* p = mov + (d0[j] * HH + h0[j]) * WW + w0[j];
            m000 = __ldg(p);             m001 = __ldg(p + 1);
            m010 = __ldg(p + WW);        m011 = __ldg(p + WW + 1);
            m100 = __ldg(p + HWX);       m101 = __ldg(p + HWX + 1);
            m110 = __ldg(p + HWX + WW);  m111 = __ldg(p + HWX + WW + 1);
        } else {
            m000 = movAt(mov, d0[j],   h0[j],   w0[j]);   m001 = movAt(mov, d0[j],   h0[j],   w0[j]+1);
            m010 = movAt(mov, d0[j],   h0[j]+1, w0[j]);   m011 = movAt(mov, d0[j],   h0[j]+1, w0[j]+1);
            m100 = movAt(mov, d0[j]+1, h0[j],   w0[j]);   m101 = movAt(mov, d0[j]+1, h0[j],   w0[j]+1);
            m110 = movAt(mov, d0[j]+1, h0[j]+1, w0[j]);   m111 = movAt(mov, d0[j]+1, h0[j]+1, w0[j]+1);
        }
        float c00 = m000 * (1.f-tw[j]) + m001 * tw[j];
        float c01 = m010 * (1.f-tw[j]) + m011 * tw[j];
        float c10 = m100 * (1.f-tw[j]) + m101 * tw[j];
        float c11 = m110 * (1.f-tw[j]) + m111 * tw[j];
        res[j] = (c00*(1.f-th[j]) + c01*th[j]) * (1.f-td[j])
               + (c10*(1.f-th[j]) + c11*th[j]) * td[j];
    }

    #pragma unroll
    for (int j = 0; j < 5; ++j)
        sum[rowbase + lane + j * 32] = res[j] + fxv[j];
}

// ---------------------------------------------------------------------------
// Shared demons math
// ---------------------------------------------------------------------------
__device__ __forceinline__ void demons_update(
    int w4, int h, int d,
    float4 sm, float4 sl, float4 sr, float4 su, float4 sd, float4 sf, float4 sb,
    float4 fx, float4 v0, float4 v1, float4 v2,
    float4& o0, float4& o1, float4& o2)
{
    #pragma unroll
    for (int j = 0; j < 4; ++j) {
        int w = w4 * 4 + j;
        float smj = ((const float*)&sm)[j];

        float left  = (j > 0) ? ((const float*)&sm)[j-1] : sl.w;
        float right = (j < 3) ? ((const float*)&sm)[j+1] : sr.x;
        float g2 = (w == 0) ? (right - smj) : (w == WW-1) ? (smj - left) : 0.5f * (right - left);

        float up = ((const float*)&su)[j], dn = ((const float*)&sd)[j];
        float g1 = (h == 0) ? (dn - smj) : (h == HH-1) ? (smj - up) : 0.5f * (dn - up);

        float fr = ((const float*)&sf)[j], bk = ((const float*)&sb)[j];
        float g0 = (d == 0) ? (bk - smj) : (d == DD-1) ? (smj - fr) : 0.5f * (bk - fr);

        float dv = smj - 2.0f * ((const float*)&fx)[j];   // warped - fix
        float denom = g0*g0 + g1*g1 + g2*g2 + dv*dv;
        float scale = (denom > 1e-6f) ? __fdividef(-dv, denom) : 0.0f;

        ((float*)&o0)[j] = ((const float*)&v0)[j] + scale * g0;
        ((float*)&o1)[j] = ((const float*)&v1)[j] + scale * g1;
        ((float*)&o2)[j] = ((const float*)&v2)[j] + scale * g2;
    }
}

// ---------------------------------------------------------------------------
// Force (iterations >= 1): IN-PLACE vf update (center-only vf access — safe).
// ---------------------------------------------------------------------------
__global__ void __launch_bounds__(256) force_kernel4(const float4* __restrict__ s,
                                                     const float4* __restrict__ fix,
                                                     float4* __restrict__ vf) {
    int i4 = blockIdx.x * 256 + threadIdx.x;
    if (i4 >= NV4) return;
    int w4 = i4 % W4;
    int h  = (i4 / W4) % HH;
    int d  = i4 / HW4;

    const float4 z4 = make_float4(0.f, 0.f, 0.f, 0.f);
    // Front-load center streams first
    float4 fx = fix[i4];
    float4 v0 = vf[i4], v1 = vf[NV4 + i4], v2 = vf[2 * NV4 + i4];
    float4 sm = s[i4];
    float4 sl = (w4 > 0)      ? s[i4 - 1]   : z4;
    float4 sr = (w4 < W4 - 1) ? s[i4 + 1]   : z4;
    float4 su = (h  > 0)      ? s[i4 - W4]  : z4;
    float4 sd = (h  < HH - 1) ? s[i4 + W4]  : z4;
    float4 sf = (d  > 0)      ? s[i4 - HW4] : z4;
    float4 sb = (d  < DD - 1) ? s[i4 + HW4] : z4;

    float4 o0, o1, o2;
    demons_update(w4, h, d, sm, sl, sr, su, sd, sf, sb, fx, v0, v1, v2, o0, o1, o2);

    vf[i4]           = o0;
    vf[NV4 + i4]     = o1;
    vf[2 * NV4 + i4] = o2;
}

// ---------------------------------------------------------------------------
// Force iteration 0: vf == 0, warped == mov; sum computed inline from inputs.
// ---------------------------------------------------------------------------
__global__ void __launch_bounds__(256) force0_kernel4(const float4* __restrict__ mov,
                                                      const float4* __restrict__ fix,
                                                      float4* __restrict__ vf_out) {
    int i4 = blockIdx.x * 256 + threadIdx.x;
    if (i4 >= NV4) return;
    int w4 = i4 % W4;
    int h  = (i4 / W4) % HH;
    int d  = i4 / HW4;

    const float4 z4 = make_float4(0.f, 0.f, 0.f, 0.f);
    #define SUMLD(off) make_float4(mov[off].x + fix[off].x, mov[off].y + fix[off].y, \
                                   mov[off].z + fix[off].z, mov[off].w + fix[off].w)
    float4 sm = SUMLD(i4);
    float4 sl = (w4 > 0)      ? SUMLD(i4 - 1)   : z4;
    float4 sr = (w4 < W4 - 1) ? SUMLD(i4 + 1)   : z4;
    float4 su = (h  > 0)      ? SUMLD(i4 - W4)  : z4;
    float4 sd = (h  < HH - 1) ? SUMLD(i4 + W4)  : z4;
    float4 sf = (d  > 0)      ? SUMLD(i4 - HW4) : z4;
    float4 sb = (d  < DD - 1) ? SUMLD(i4 + HW4) : z4;
    #undef SUMLD
    float4 fx = fix[i4];

    float4 o0, o1, o2;
    demons_update(w4, h, d, sm, sl, sr, su, sd, sf, sb, fx, z4, z4, z4, o0, o1, o2);

    vf_out[i4]           = o0;
    vf_out[NV4 + i4]     = o1;
    vf_out[2 * NV4 + i4] = o2;
}

// ---------------------------------------------------------------------------
// Fused W+H Gaussian smoothing, single smem buffer.
// ---------------------------------------------------------------------------
#define TROWS 36
#define IROWS 32
#define NT_HW 5   // 160 / 32

__global__ void __launch_bounds__(256) smoothHW_kernel(const float4* __restrict__ in,
                                                       float4* __restrict__ out) {
    __shared__ float4 s1[TROWS * W4];

    int b  = blockIdx.x;
    int ht = b % NT_HW;
    int d  = (b / NT_HW) % DD;
    int c  = b / (NT_HW * DD);
    int h0 = ht * IROWS;

    const float4* src = in  + (size_t)c * NV4 + (size_t)d * HW4;
    float4*       dst = out + (size_t)c * NV4 + (size_t)d * HW4;
    const float4 z4 = make_float4(0.f, 0.f, 0.f, 0.f);

    for (int t = threadIdx.x; t < TROWS * W4; t += 256) {
        int r  = t / W4;
        int cc = t % W4;
        int hg = h0 - 2 + r;
        float4 o;
        if ((unsigned)hg < HH) {
            const float4* row = src + hg * W4;
            float4 m = __ldg(row + cc);
            float4 l = (cc > 0)      ? __ldg(row + cc - 1) : z4;
            float4 r2 = (cc < W4 - 1) ? __ldg(row + cc + 1) : z4;
            o.x = GW2*l.z + GW1*l.w + GW0*m.x + GW1*m.y + GW2*m.z;
            o.y = GW2*l.w + GW1*m.x + GW0*m.y + GW1*m.z + GW2*m.w;
            o.z = GW2*m.x + GW1*m.y + GW0*m.z + GW1*m.w + GW2*r2.x;
            o.w = GW2*m.y + GW1*m.z + GW0*m.w + GW1*r2.x + GW2*r2.y;
        } else {
            o = z4;
        }
        s1[t] = o;
    }
    __syncthreads();

    for (int t = threadIdx.x; t < IROWS * W4; t += 256) {
        int r  = t / W4 + 2;
        int cc = t % W4;
        float4 a = s1[(r - 2) * W4 + cc];
        float4 b2 = s1[(r - 1) * W4 + cc];
        float4 m = s1[r * W4 + cc];
        float4 e = s1[(r + 1) * W4 + cc];
        float4 f = s1[(r + 2) * W4 + cc];
        float4 o;
        o.x = GW2*(a.x + f.x) + GW1*(b2.x + e.x) + GW0*m.x;
        o.y = GW2*(a.y + f.y) + GW1*(b2.y + e.y) + GW0*m.y;
        o.z = GW2*(a.z + f.z) + GW1*(b2.z + e.z) + GW0*m.z;
        o.w = GW2*(a.w + f.w) + GW1*(b2.w + e.w) + GW0*m.w;
        dst[(h0 + r - 2) * W4 + cc] = o;
    }
}

// ---------------------------------------------------------------------------
// D-axis smoothing: 2 column streams per thread (2x MLP), 16 outputs each.
// ---------------------------------------------------------------------------
#define DSEG 16
#define NDSEG (DD / DSEG)   // 8
#define HALFC (HW4 / 2)     // 3200

__global__ void __launch_bounds__(256) smoothD_slide2(const float4* __restrict__ in,
                                                      float4* __restrict__ out) {
    int gid = blockIdx.x * 256 + threadIdx.x;
    int col = gid % HALFC;
    int seg = (gid / HALFC) % NDSEG;
    int c   = gid / (HALFC * NDSEG);
    const float4 z4 = make_float4(0.f, 0.f, 0.f, 0.f);

    const float4* pa = in  + (size_t)c * NV4 + col;
    const float4* pb = pa + HALFC;
    float4*       qa = out + (size_t)c * NV4 + col;
    float4*       qb = qa + HALFC;
    int d0 = seg * DSEG;

    float4 a0, a1, a2, a3, a4, b0, b1, b2, b3, b4;
    if (d0 >= 2) { a0 = pa[(size_t)(d0-2)*HW4]; b0 = pb[(size_t)(d0-2)*HW4]; }
    else         { a0 = z4; b0 = z4; }
    if (d0 >= 1) { a1 = pa[(size_t)(d0-1)*HW4]; b1 = pb[(size_t)(d0-1)*HW4]; }
    else         { a1 = z4; b1 = z4; }
    a2 = pa[(size_t)d0*HW4];     b2 = pb[(size_t)d0*HW4];
    a3 = pa[(size_t)(d0+1)*HW4]; b3 = pb[(size_t)(d0+1)*HW4];
    a4 = pa[(size_t)(d0+2)*HW4]; b4 = pb[(size_t)(d0+2)*HW4];

    #pragma unroll
    for (int dd = 0; dd < DSEG; ++dd) {
        int d = d0 + dd;
        float4 oa, ob;
        oa.x = GW2*(a0.x + a4.x) + GW1*(a1.x + a3.x) + GW0*a2.x;
        oa.y = GW2*(a0.y + a4.y) + GW1*(a1.y + a3.y) + GW0*a2.y;
        oa.z = GW2*(a0.z + a4.z) + GW1*(a1.z + a3.z) + GW0*a2.z;
        oa.w = GW2*(a0.w + a4.w) + GW1*(a1.w + a3.w) + GW0*a2.w;
        ob.x = GW2*(b0.x + b4.x) + GW1*(b1.x + b3.x) + GW0*b2.x;
        ob.y = GW2*(b0.y + b4.y) + GW1*(b1.y + b3.y) + GW0*b2.y;
        ob.z = GW2*(b0.z + b4.z) + GW1*(b1.z + b3.z) + GW0*b2.z;
        ob.w = GW2*(b0.w + b4.w) + GW1*(b1.w + b3.w) + GW0*b2.w;
        qa[(size_t)d * HW4] = oa;
        qb[(size_t)d * HW4] = ob;
        a0 = a1; a1 = a2; a2 = a3; a3 = a4;
        b0 = b1; b1 = b2; b2 = b3; b3 = b4;
        if (d + 3 < DD) {
            a4 = pa[(size_t)(d + 3) * HW4];
            b4 = pb[(size_t)(d + 3) * HW4];
        } else {
            a4 = z4; b4 = z4;
        }
    }
}

extern "C" void kernel_launch(void* const* d_in, const int* in_sizes, int n_in,
                              void* d_out, int out_size) {
    const float* mov = (const float*)d_in[0];
    const float* fixf = (const float*)d_in[1];
    const float4* fix = (const float4*)d_in[1];
    float4* out4 = (float4*)d_out;

    float *vfA, *vfC, *sum;
    cudaGetSymbolAddress((void**)&vfA, g_vfA);
    cudaGetSymbolAddress((void**)&vfC, g_vfC);
    cudaGetSymbolAddress((void**)&sum, g_sum);

    const int blocksN4  = NV4 / 256;                   // 3200
    const int blocksHW  = 3 * DD * NT_HW;              // 1920
    const int blocksD   = (3 * NDSEG * HALFC) / 256;   // 300
    const int blocksRow = (DD * HH) / 8;               // 2560 (8 warps/block)

    for (int it = 0; it < NITER; ++it) {
        if (it == 0) {
            force0_kernel4<<<blocksN4, 256>>>((const float4*)mov, fix, (float4*)vfA);
        } else {
            warp_kernel_row<<<blocksRow, 256>>>(mov, fixf, vfA, sum);
            force_kernel4<<<blocksN4, 256>>>((const float4*)sum, fix, (float4*)vfA);
        }
        smoothHW_kernel<<<blocksHW, 256>>>((const float4*)vfA, (float4*)vfC);
        float4* dst = (it == NITER - 1) ? out4 : (float4*)vfA;
        smoothD_slide2<<<blocksD, 256>>>((const float4*)vfC, dst);
    }
}